// round 3
// baseline (speedup 1.0000x reference)
#include <cuda_runtime.h>

#define N_CELL 50000
#define N_NET 10000
#define N_GCELL 20000
#define NE 100000
#define D 32
#define DP 16
#define PB 17            // 16 edge-feature channels + 1 bias channel (b_topo)
#define AW (PB * D)      // 544

// ---------------- scratch (static device globals; no allocation) ----------------
__device__ float g_A1[N_NET * AW];        // per-net   NNConv table  (~21.8 MB)
__device__ float g_A2[N_GCELL * AW];      // per-gcell NNConv table  (~43.5 MB)
__device__ float g_feat_pins[N_CELL * D];
__device__ float g_feat_pt[N_CELL * D];
__device__ float g_feat_conn[N_GCELL * D];
__device__ float g_acc_net[N_NET * D];
__device__ float g_acc_conn[N_GCELL * D];
__device__ float g_acc_ptg[N_GCELL * D];
__device__ float g_acc_pinned[N_CELL * D];
__device__ float g_acc_pf[N_CELL * D];
__device__ int g_deg_pins_src[N_CELL];
__device__ int g_deg_pins_dst[N_NET];
__device__ int g_deg_conn_src[N_GCELL];
__device__ int g_deg_conn_dst[N_GCELL];
__device__ int g_deg_pt_src[N_CELL];
__device__ int g_deg_pt_dst[N_GCELL];
__device__ int g_deg_pinned_dst[N_CELL];
__device__ int g_deg_pf_dst[N_CELL];

// ---------------- zero everything that accumulates ----------------
__global__ void zero_kernel() {
    int stride = gridDim.x * blockDim.x;
    int i0 = blockIdx.x * blockDim.x + threadIdx.x;
    for (int i = i0; i < N_NET * D; i += stride) g_acc_net[i] = 0.f;
    for (int i = i0; i < N_GCELL * D; i += stride) { g_acc_conn[i] = 0.f; g_acc_ptg[i] = 0.f; }
    for (int i = i0; i < N_CELL * D; i += stride) { g_acc_pinned[i] = 0.f; g_acc_pf[i] = 0.f; }
    for (int i = i0; i < N_CELL; i += stride) {
        g_deg_pins_src[i] = 0; g_deg_pt_src[i] = 0;
        g_deg_pinned_dst[i] = 0; g_deg_pf_dst[i] = 0;
    }
    for (int i = i0; i < N_NET; i += stride) g_deg_pins_dst[i] = 0;
    for (int i = i0; i < N_GCELL; i += stride) {
        g_deg_conn_src[i] = 0; g_deg_conn_dst[i] = 0; g_deg_pt_dst[i] = 0;
    }
}

// ---------------- degree histograms ----------------
__global__ void degree_kernel(const int* __restrict__ pins_src, const int* __restrict__ pins_dst,
                              const int* __restrict__ pinned_dst,
                              const int* __restrict__ conn_src, const int* __restrict__ conn_dst,
                              const int* __restrict__ pt_src, const int* __restrict__ pt_dst,
                              const int* __restrict__ pf_dst) {
    int e = blockIdx.x * blockDim.x + threadIdx.x;
    if (e >= NE) return;
    atomicAdd(&g_deg_pins_src[pins_src[e]], 1);
    atomicAdd(&g_deg_pins_dst[pins_dst[e]], 1);
    atomicAdd(&g_deg_pinned_dst[pinned_dst[e]], 1);
    atomicAdd(&g_deg_conn_src[conn_src[e]], 1);
    atomicAdd(&g_deg_conn_dst[conn_dst[e]], 1);
    atomicAdd(&g_deg_pt_src[pt_src[e]], 1);
    atomicAdd(&g_deg_pt_dst[pt_dst[e]], 1);
    atomicAdd(&g_deg_pf_dst[pf_dst[e]], 1);
}

// ---------------- GraphConv source-side transform: (x * deg^-1/2) @ W ----------------
// mode 0: X=node_feat, WA=W_pins -> g_feat_pins (deg_pins_src), WB=W_pt -> g_feat_pt (deg_pt_src)
// mode 1: X=hanna_feat, WA=W_connect -> g_feat_conn (deg_conn_src)
__global__ void xform2_kernel(const float* __restrict__ X, int n,
                              const float* __restrict__ WA, const float* __restrict__ WB, int mode) {
    __shared__ float WsA[D * D];
    __shared__ float WsB[D * D];
    int tid = threadIdx.x;
    bool hasB = (mode == 0);
    for (int i = tid; i < D * D; i += blockDim.x) {
        WsA[i] = WA[i];
        if (hasB) WsB[i] = WB[i];
    }
    __syncthreads();
    int warp = tid >> 5, o = tid & 31;
    int r = blockIdx.x * (blockDim.x >> 5) + warp;
    if (r >= n) return;
    float xv = X[r * D + o];
    float aA = 0.f, aB = 0.f;
#pragma unroll
    for (int i = 0; i < D; i++) {
        float xi = __shfl_sync(0xffffffffu, xv, i);
        aA += xi * WsA[i * D + o];
        if (hasB) aB += xi * WsB[i * D + o];
    }
    if (mode == 0) {
        float sA = rsqrtf(fmaxf((float)g_deg_pins_src[r], 1.f));
        float sB = rsqrtf(fmaxf((float)g_deg_pt_src[r], 1.f));
        g_feat_pins[r * D + o] = aA * sA;
        g_feat_pt[r * D + o] = aB * sB;
    } else {
        float sA = rsqrtf(fmaxf((float)g_deg_conn_src[r], 1.f));
        g_feat_conn[r * D + o] = aA * sA;
    }
}

// ---------------- NNConv per-source table: A[r, p*32+o] = sum_i X[r,i]*W_topo[p, i*32+o] ----------------
// p == 16 is the b_topo bias channel (edge "feature" value 1.0).
// 4 nodes per block-pass to amortize the Wt smem reads.
__global__ void aker(const float* __restrict__ X, int n,
                     const float* __restrict__ W_topo, const float* __restrict__ b_topo, int mode) {
    extern __shared__ float sh[];
    float* Wt = sh;              // [32][AW]
    float* xs = sh + 32 * AW;    // [4][32]
    float* A = mode ? g_A2 : g_A1;
    int tid = threadIdx.x;
    for (int idx = tid; idx < 32 * AW; idx += blockDim.x) {
        int i = idx / AW;
        int j = idx - i * AW;
        int p = j >> 5;
        int o = j & 31;
        Wt[idx] = (p < DP) ? W_topo[p * (D * D) + i * D + o] : b_topo[i * D + o];
    }
    __syncthreads();
    int base = blockIdx.x * 4;
    if (base >= n) return;
    if (tid < 128) {
        int r = base + (tid >> 5);
        xs[tid] = (r < n) ? X[r * D + (tid & 31)] : 0.f;
    }
    __syncthreads();
    int j = tid;  // blockDim.x == AW
    float a0 = 0.f, a1 = 0.f, a2 = 0.f, a3 = 0.f;
#pragma unroll
    for (int i = 0; i < D; i++) {
        float w = Wt[i * AW + j];
        a0 += w * xs[0 * D + i];
        a1 += w * xs[1 * D + i];
        a2 += w * xs[2 * D + i];
        a3 += w * xs[3 * D + i];
    }
    if (base + 0 < n) A[(base + 0) * AW + j] = a0;
    if (base + 1 < n) A[(base + 1) * AW + j] = a1;
    if (base + 2 < n) A[(base + 2) * AW + j] = a2;
    if (base + 3 < n) A[(base + 3) * AW + j] = a3;
}

// ---------------- GraphConv edge scatter: acc[dst] += feat[src]  (warp = edge) ----------------
__global__ void gconv_edge_kernel(const int* __restrict__ src, const int* __restrict__ dst, int mode) {
    int idx = blockIdx.x * blockDim.x + threadIdx.x;
    if (idx >= NE * 32) return;
    int e = idx >> 5, o = idx & 31;
    const float* feat = (mode == 0) ? g_feat_pins : (mode == 1) ? g_feat_conn : g_feat_pt;
    float* acc = (mode == 0) ? g_acc_net : (mode == 1) ? g_acc_conn : g_acc_ptg;
    int s = src[e], d2 = dst[e];
    atomicAdd(&acc[d2 * D + o], feat[s * D + o]);
}

// ---------------- NNConv edge: m[o] = sum_p ef[e,p]*A[src,p*32+o]; acc[dst] += m ----------------
__global__ void nnconv_edge_kernel(const int* __restrict__ src, const int* __restrict__ dst,
                                   const float* __restrict__ ef, int mode) {
    int idx = blockIdx.x * blockDim.x + threadIdx.x;
    int e = idx >> 5;
    if (e >= NE) return;
    int o = threadIdx.x & 31;
    const float* A = mode ? g_A2 : g_A1;
    float* acc = mode ? g_acc_pf : g_acc_pinned;
    int s = src[e], d2 = dst[e];
    float efv = (o < DP) ? ef[e * DP + o] : 1.f;  // lane 16 carries the bias channel
    const float* Ar = A + s * AW;
    float m = 0.f;
#pragma unroll
    for (int p = 0; p < PB; p++) {
        float ep = __shfl_sync(0xffffffffu, efv, p);
        m += ep * Ar[p * D + o];
    }
    atomicAdd(&acc[d2 * D + o], m);
}

// ---------------- finalize ----------------
__global__ void final_cell_kernel(float* __restrict__ out,
                                  const float* __restrict__ b_pinned, const float* __restrict__ b_pf) {
    int idx = blockIdx.x * blockDim.x + threadIdx.x;
    if (idx >= N_CELL * D) return;
    int c = idx >> 5, o = idx & 31;
    float inv1 = 1.f / fmaxf((float)g_deg_pinned_dst[c], 1.f);
    float inv2 = 1.f / fmaxf((float)g_deg_pf_dst[c], 1.f);
    out[idx] = g_acc_pinned[idx] * inv1 + b_pinned[o] + g_acc_pf[idx] * inv2 + b_pf[o];
}

__global__ void final_net_kernel(float* __restrict__ out, const float* __restrict__ net_feat,
                                 const float* __restrict__ W_net, const float* __restrict__ b_net,
                                 const float* __restrict__ b_pins) {
    __shared__ float Ws[D * D];
    int tid = threadIdx.x;
    for (int i = tid; i < D * D; i += blockDim.x) Ws[i] = W_net[i];
    __syncthreads();
    int warp = tid >> 5, o = tid & 31;
    int r = blockIdx.x * (blockDim.x >> 5) + warp;
    if (r >= N_NET) return;
    float xv = net_feat[r * D + o];
    float acc = 0.f;
#pragma unroll
    for (int i = 0; i < D; i++) acc += __shfl_sync(0xffffffffu, xv, i) * Ws[i * D + o];
    float s = rsqrtf(fmaxf((float)g_deg_pins_dst[r], 1.f));
    out[N_CELL * D + r * D + o] = g_acc_net[r * D + o] * s + b_pins[o] + acc + b_net[o];
}

__global__ void final_gcell_kernel(float* __restrict__ out,
                                   const float* __restrict__ b_connect, const float* __restrict__ b_pt) {
    int idx = blockIdx.x * blockDim.x + threadIdx.x;
    if (idx >= N_GCELL * D) return;
    int g = idx >> 5, o = idx & 31;
    float s1 = rsqrtf(fmaxf((float)g_deg_conn_dst[g], 1.f));
    float s2 = rsqrtf(fmaxf((float)g_deg_pt_dst[g], 1.f));
    out[(N_CELL + N_NET) * D + idx] =
        g_acc_conn[idx] * s1 + b_connect[o] + g_acc_ptg[idx] * s2 + b_pt[o];
}

// ---------------- launch ----------------
extern "C" void kernel_launch(void* const* d_in, const int* in_sizes, int n_in,
                              void* d_out, int out_size) {
    const float* node_feat   = (const float*)d_in[0];
    const float* net_feat    = (const float*)d_in[1];
    const float* pin_feat    = (const float*)d_in[2];
    const float* hanna_feat  = (const float*)d_in[3];
    const float* edge_feat   = (const float*)d_in[4];
    const int* pins_src      = (const int*)d_in[5];
    const int* pins_dst      = (const int*)d_in[6];
    const int* pinned_src    = (const int*)d_in[7];
    const int* pinned_dst    = (const int*)d_in[8];
    const int* connect_src   = (const int*)d_in[9];
    const int* connect_dst   = (const int*)d_in[10];
    const int* pt_src        = (const int*)d_in[11];
    const int* pt_dst        = (const int*)d_in[12];
    const int* pf_src        = (const int*)d_in[13];
    const int* pf_dst        = (const int*)d_in[14];
    const float* W_net       = (const float*)d_in[15];
    const float* b_net       = (const float*)d_in[16];
    const float* W_topo      = (const float*)d_in[17];
    const float* b_topo      = (const float*)d_in[18];
    const float* W_pins      = (const float*)d_in[19];
    const float* b_pins      = (const float*)d_in[20];
    const float* W_connect   = (const float*)d_in[21];
    const float* b_connect   = (const float*)d_in[22];
    const float* W_pt        = (const float*)d_in[23];
    const float* b_pt        = (const float*)d_in[24];
    const float* b_pinned    = (const float*)d_in[25];
    const float* b_pf        = (const float*)d_in[26];
    float* out = (float*)d_out;

    zero_kernel<<<1024, 256>>>();
    degree_kernel<<<(NE + 255) / 256, 256>>>(pins_src, pins_dst, pinned_dst,
                                             connect_src, connect_dst, pt_src, pt_dst, pf_dst);
    xform2_kernel<<<(N_CELL + 7) / 8, 256>>>(node_feat, N_CELL, W_pins, W_pt, 0);
    xform2_kernel<<<(N_GCELL + 7) / 8, 256>>>(hanna_feat, N_GCELL, W_connect, W_connect, 1);

    int ash = (32 * AW + 4 * D) * (int)sizeof(float);
    cudaFuncSetAttribute(aker, cudaFuncAttributeMaxDynamicSharedMemorySize, ash);
    aker<<<(N_NET + 3) / 4, AW, ash>>>(net_feat, N_NET, W_topo, b_topo, 0);
    aker<<<(N_GCELL + 3) / 4, AW, ash>>>(hanna_feat, N_GCELL, W_topo, b_topo, 1);

    gconv_edge_kernel<<<NE * 32 / 256, 256>>>(pins_src, pins_dst, 0);
    gconv_edge_kernel<<<NE * 32 / 256, 256>>>(connect_src, connect_dst, 1);
    gconv_edge_kernel<<<NE * 32 / 256, 256>>>(pt_src, pt_dst, 2);
    nnconv_edge_kernel<<<NE * 32 / 256, 256>>>(pinned_src, pinned_dst, pin_feat, 0);
    nnconv_edge_kernel<<<NE * 32 / 256, 256>>>(pf_src, pf_dst, edge_feat, 1);

    final_cell_kernel<<<(N_CELL * D + 255) / 256, 256>>>(out, b_pinned, b_pf);
    final_net_kernel<<<(N_NET + 7) / 8, 256>>>(out, net_feat, W_net, b_net, b_pins);
    final_gcell_kernel<<<(N_GCELL * D + 255) / 256, 256>>>(out, b_connect, b_pt);
}

// round 8
// speedup vs baseline: 1.7493x; 1.7493x over previous
#include <cuda_runtime.h>

#define N_CELL 50000
#define N_NET 10000
#define N_GCELL 20000
#define NE 100000
#define D 32
#define DP 16
#define PB 17            // 16 edge-feature channels + 1 bias channel (b_topo)
#define AW (PB * D)      // 544

// ---------------- scratch (static device globals; no allocation) ----------------
__device__ float g_A1[N_NET * AW];        // per-net   NNConv table  (~21.8 MB)
__device__ float g_A2[N_GCELL * AW];      // per-gcell NNConv table  (~43.5 MB)
__device__ float g_feat_pins[N_CELL * D];
__device__ float g_feat_pt[N_CELL * D];
__device__ float g_feat_conn[N_GCELL * D];
__device__ float g_acc_net[N_NET * D];
__device__ float g_acc_conn[N_GCELL * D];
__device__ float g_acc_ptg[N_GCELL * D];
__device__ float g_acc_pinned[N_CELL * D];
__device__ float g_acc_pf[N_CELL * D];
__device__ int g_deg_pins_src[N_CELL];
__device__ int g_deg_pins_dst[N_NET];
__device__ int g_deg_conn_src[N_GCELL];
__device__ int g_deg_conn_dst[N_GCELL];
__device__ int g_deg_pt_src[N_CELL];
__device__ int g_deg_pt_dst[N_GCELL];
__device__ int g_deg_pinned_dst[N_CELL];
__device__ int g_deg_pf_dst[N_CELL];

// ---------------- zero everything that accumulates ----------------
__global__ void zero_kernel() {
    int stride = gridDim.x * blockDim.x;
    int i0 = blockIdx.x * blockDim.x + threadIdx.x;
    for (int i = i0; i < N_NET * D; i += stride) g_acc_net[i] = 0.f;
    for (int i = i0; i < N_GCELL * D; i += stride) { g_acc_conn[i] = 0.f; g_acc_ptg[i] = 0.f; }
    for (int i = i0; i < N_CELL * D; i += stride) { g_acc_pinned[i] = 0.f; g_acc_pf[i] = 0.f; }
    for (int i = i0; i < N_CELL; i += stride) {
        g_deg_pins_src[i] = 0; g_deg_pt_src[i] = 0;
        g_deg_pinned_dst[i] = 0; g_deg_pf_dst[i] = 0;
    }
    for (int i = i0; i < N_NET; i += stride) g_deg_pins_dst[i] = 0;
    for (int i = i0; i < N_GCELL; i += stride) {
        g_deg_conn_src[i] = 0; g_deg_conn_dst[i] = 0; g_deg_pt_dst[i] = 0;
    }
}

// ---------------- degree histograms ----------------
__global__ void degree_kernel(const int* __restrict__ pins_src, const int* __restrict__ pins_dst,
                              const int* __restrict__ pinned_dst,
                              const int* __restrict__ conn_src, const int* __restrict__ conn_dst,
                              const int* __restrict__ pt_src, const int* __restrict__ pt_dst,
                              const int* __restrict__ pf_dst) {
    int e = blockIdx.x * blockDim.x + threadIdx.x;
    if (e >= NE) return;
    atomicAdd(&g_deg_pins_src[pins_src[e]], 1);
    atomicAdd(&g_deg_pins_dst[pins_dst[e]], 1);
    atomicAdd(&g_deg_pinned_dst[pinned_dst[e]], 1);
    atomicAdd(&g_deg_conn_src[conn_src[e]], 1);
    atomicAdd(&g_deg_conn_dst[conn_dst[e]], 1);
    atomicAdd(&g_deg_pt_src[pt_src[e]], 1);
    atomicAdd(&g_deg_pt_dst[pt_dst[e]], 1);
    atomicAdd(&g_deg_pf_dst[pf_dst[e]], 1);
}

// ---------------- GraphConv src transform: (x * deg^-1/2) @ W (register-W, LDS.128 bcast x)
// mode 0: X=node_feat -> g_feat_pins (W_pins, deg_pins_src), g_feat_pt (W_pt, deg_pt_src)
// mode 1: X=hanna_feat -> g_feat_conn (W_connect, deg_conn_src)
__global__ __launch_bounds__(256) void xform3(const float* __restrict__ X, int n,
                                              const float* __restrict__ WA,
                                              const float* __restrict__ WB, int mode) {
    __shared__ __align__(16) float xs[256];
    int tid = threadIdx.x, o = tid & 31, w = tid >> 5;
    bool hasB = (mode == 0);
    float wa[32], wb[32];
#pragma unroll
    for (int i = 0; i < 32; i++) {
        wa[i] = WA[i * 32 + o];
        wb[i] = hasB ? WB[i * 32 + o] : 0.f;
    }
    int ngroups = (n + 7) >> 3;
    for (int g = blockIdx.x; g < ngroups; g += gridDim.x) {
        int base = g * 8;
        __syncthreads();
        {
            int r = base + w;
            xs[tid] = (r < n) ? X[r * 32 + o] : 0.f;
        }
        __syncthreads();
        int r = base + w;
        if (r < n) {
            float aA = 0.f, aB = 0.f;
#pragma unroll
            for (int i = 0; i < 32; i += 4) {
                float4 x4 = *(const float4*)&xs[w * 32 + i];
                aA = fmaf(wa[i], x4.x, aA);
                aA = fmaf(wa[i + 1], x4.y, aA);
                aA = fmaf(wa[i + 2], x4.z, aA);
                aA = fmaf(wa[i + 3], x4.w, aA);
                if (hasB) {
                    aB = fmaf(wb[i], x4.x, aB);
                    aB = fmaf(wb[i + 1], x4.y, aB);
                    aB = fmaf(wb[i + 2], x4.z, aB);
                    aB = fmaf(wb[i + 3], x4.w, aB);
                }
            }
            if (mode == 0) {
                float sA = rsqrtf(fmaxf((float)g_deg_pins_src[r], 1.f));
                float sB = rsqrtf(fmaxf((float)g_deg_pt_src[r], 1.f));
                g_feat_pins[r * D + o] = aA * sA;
                g_feat_pt[r * D + o] = aB * sB;
            } else {
                float sA = rsqrtf(fmaxf((float)g_deg_conn_src[r], 1.f));
                g_feat_conn[r * D + o] = aA * sA;
            }
        }
    }
}

// ---------------- NNConv per-source table: A[r, p*32+o] = sum_i X[r,i]*W_topo[p, i*32+o]
// Register-resident W column per thread; x staged as node-PAIRS in smem, read via
// broadcast LDS.128; packed fma.rn.f32x2 computes two nodes per instruction.
// Virtual groups: g<2500 -> nets (4 per group), g>=2500 -> gcells.
__global__ __launch_bounds__(544) void aker3(const float* __restrict__ Xnet,
                                             const float* __restrict__ Xg,
                                             const float* __restrict__ W_topo,
                                             const float* __restrict__ b_topo) {
    __shared__ __align__(16) float xs[128];  // [pair(2)][i(32)][half(2)]
    int j = threadIdx.x;  // 0..543
    int p_ = j >> 5, o = j & 31;
    float w[32];
#pragma unroll
    for (int i = 0; i < 32; i++)
        w[i] = (p_ < DP) ? W_topo[p_ * 1024 + i * 32 + o] : b_topo[i * 32 + o];

    const int NGROUPS = (N_NET + N_GCELL) / 4;  // 7500
    for (int g = blockIdx.x; g < NGROUPS; g += gridDim.x) {
        bool isnet = (g < N_NET / 4);
        const float* X = isnet ? Xnet : Xg;
        float* A = isnet ? g_A1 : g_A2;
        int base = isnet ? g * 4 : (g - N_NET / 4) * 4;
        __syncthreads();
        if (j < 128) {
            int k = j >> 5, i = j & 31;
            xs[(k >> 1) * 64 + i * 2 + (k & 1)] = X[(base + k) * 32 + i];
        }
        __syncthreads();
        unsigned long long a0 = 0ull, a1 = 0ull;  // packed (0.f, 0.f)
#pragma unroll
        for (int i = 0; i < 32; i += 2) {
            ulonglong2 v0 = *(const ulonglong2*)&xs[0 * 64 + i * 2];  // pair(n0,n1): i, i+1
            ulonglong2 v1 = *(const ulonglong2*)&xs[1 * 64 + i * 2];  // pair(n2,n3): i, i+1
            unsigned long long wp0, wp1;
            asm("mov.b64 %0, {%1, %1};" : "=l"(wp0) : "f"(w[i]));
            asm("mov.b64 %0, {%1, %1};" : "=l"(wp1) : "f"(w[i + 1]));
            asm("fma.rn.f32x2 %0, %1, %2, %0;" : "+l"(a0) : "l"(wp0), "l"(v0.x));
            asm("fma.rn.f32x2 %0, %1, %2, %0;" : "+l"(a1) : "l"(wp0), "l"(v1.x));
            asm("fma.rn.f32x2 %0, %1, %2, %0;" : "+l"(a0) : "l"(wp1), "l"(v0.y));
            asm("fma.rn.f32x2 %0, %1, %2, %0;" : "+l"(a1) : "l"(wp1), "l"(v1.y));
        }
        float f00, f01, f10, f11;
        asm("mov.b64 {%0, %1}, %2;" : "=f"(f00), "=f"(f01) : "l"(a0));
        asm("mov.b64 {%0, %1}, %2;" : "=f"(f10), "=f"(f11) : "l"(a1));
        A[(base + 0) * AW + j] = f00;
        A[(base + 1) * AW + j] = f01;
        A[(base + 2) * AW + j] = f10;
        A[(base + 3) * AW + j] = f11;
    }
}

// ---------------- fused edge scatter: 3x GraphConv + 2x NNConv in one launch ----------------
__global__ __launch_bounds__(256) void fused_edge(
    const int* __restrict__ pins_src, const int* __restrict__ pins_dst,
    const int* __restrict__ conn_src, const int* __restrict__ conn_dst,
    const int* __restrict__ pt_src, const int* __restrict__ pt_dst,
    const int* __restrict__ pinned_src, const int* __restrict__ pinned_dst,
    const int* __restrict__ pf_src, const int* __restrict__ pf_dst,
    const float* __restrict__ pin_feat, const float* __restrict__ edge_feat) {
    const int BPS = NE * 32 / 256;  // 12500 blocks per segment
    int seg = blockIdx.x / BPS;
    int idx = (blockIdx.x - seg * BPS) * 256 + threadIdx.x;
    int e = idx >> 5, o = idx & 31;
    if (seg < 3) {
        const int* src = (seg == 0) ? pins_src : (seg == 1) ? conn_src : pt_src;
        const int* dst = (seg == 0) ? pins_dst : (seg == 1) ? conn_dst : pt_dst;
        const float* feat = (seg == 0) ? g_feat_pins : (seg == 1) ? g_feat_conn : g_feat_pt;
        float* acc = (seg == 0) ? g_acc_net : (seg == 1) ? g_acc_conn : g_acc_ptg;
        int s = src[e], d2 = dst[e];
        atomicAdd(&acc[d2 * D + o], feat[s * D + o]);
    } else {
        const int* src = (seg == 3) ? pinned_src : pf_src;
        const int* dst = (seg == 3) ? pinned_dst : pf_dst;
        const float* ef = (seg == 3) ? pin_feat : edge_feat;
        const float* A = (seg == 3) ? g_A1 : g_A2;
        float* acc = (seg == 3) ? g_acc_pinned : g_acc_pf;
        int s = src[e], d2 = dst[e];
        float efv = (o < DP) ? ef[e * DP + o] : 1.f;  // lane 16 = bias channel
        const float* Ar = A + s * AW;
        float m = 0.f;
#pragma unroll
        for (int p = 0; p < PB; p++) {
            float ep = __shfl_sync(0xffffffffu, efv, p);
            m = fmaf(ep, Ar[p * D + o], m);
        }
        atomicAdd(&acc[d2 * D + o], m);
    }
}

// ---------------- fused finalize: cell | net | gcell segments ----------------
__global__ __launch_bounds__(256) void fused_final(
    float* __restrict__ out, const float* __restrict__ net_feat,
    const float* __restrict__ W_net, const float* __restrict__ b_net,
    const float* __restrict__ b_pins, const float* __restrict__ b_pinned,
    const float* __restrict__ b_pf, const float* __restrict__ b_connect,
    const float* __restrict__ b_pt) {
    const int CB = N_CELL * D / 256;  // 6250
    const int NB = N_NET / 8;         // 1250
    __shared__ float Ws[D * D];
    int tid = threadIdx.x;
    int b = blockIdx.x;
    if (b < CB) {
        int idx = b * 256 + tid;
        int c = idx >> 5, o = idx & 31;
        float inv1 = 1.f / fmaxf((float)g_deg_pinned_dst[c], 1.f);
        float inv2 = 1.f / fmaxf((float)g_deg_pf_dst[c], 1.f);
        out[idx] = g_acc_pinned[idx] * inv1 + b_pinned[o] + g_acc_pf[idx] * inv2 + b_pf[o];
    } else if (b < CB + NB) {
        for (int i = tid; i < D * D; i += 256) Ws[i] = W_net[i];
        __syncthreads();
        int warp = tid >> 5, o = tid & 31;
        int r = (b - CB) * 8 + warp;
        float xv = net_feat[r * D + o];
        float acc = 0.f;
#pragma unroll
        for (int i = 0; i < D; i++)
            acc = fmaf(__shfl_sync(0xffffffffu, xv, i), Ws[i * D + o], acc);
        float s = rsqrtf(fmaxf((float)g_deg_pins_dst[r], 1.f));
        out[N_CELL * D + r * D + o] = g_acc_net[r * D + o] * s + b_pins[o] + acc + b_net[o];
    } else {
        int idx = (b - CB - NB) * 256 + tid;
        int g = idx >> 5, o = idx & 31;
        float s1 = rsqrtf(fmaxf((float)g_deg_conn_dst[g], 1.f));
        float s2 = rsqrtf(fmaxf((float)g_deg_pt_dst[g], 1.f));
        out[(N_CELL + N_NET) * D + idx] =
            g_acc_conn[idx] * s1 + b_connect[o] + g_acc_ptg[idx] * s2 + b_pt[o];
    }
}

// ---------------- launch ----------------
extern "C" void kernel_launch(void* const* d_in, const int* in_sizes, int n_in,
                              void* d_out, int out_size) {
    const float* node_feat   = (const float*)d_in[0];
    const float* net_feat    = (const float*)d_in[1];
    const float* pin_feat    = (const float*)d_in[2];
    const float* hanna_feat  = (const float*)d_in[3];
    const float* edge_feat   = (const float*)d_in[4];
    const int* pins_src      = (const int*)d_in[5];
    const int* pins_dst      = (const int*)d_in[6];
    const int* pinned_src    = (const int*)d_in[7];
    const int* pinned_dst    = (const int*)d_in[8];
    const int* connect_src   = (const int*)d_in[9];
    const int* connect_dst   = (const int*)d_in[10];
    const int* pt_src        = (const int*)d_in[11];
    const int* pt_dst        = (const int*)d_in[12];
    const int* pf_src        = (const int*)d_in[13];
    const int* pf_dst        = (const int*)d_in[14];
    const float* W_net       = (const float*)d_in[15];
    const float* b_net       = (const float*)d_in[16];
    const float* W_topo      = (const float*)d_in[17];
    const float* b_topo      = (const float*)d_in[18];
    const float* W_pins      = (const float*)d_in[19];
    const float* b_pins      = (const float*)d_in[20];
    const float* W_connect   = (const float*)d_in[21];
    const float* b_connect   = (const float*)d_in[22];
    const float* W_pt        = (const float*)d_in[23];
    const float* b_pt        = (const float*)d_in[24];
    const float* b_pinned    = (const float*)d_in[25];
    const float* b_pf        = (const float*)d_in[26];
    float* out = (float*)d_out;

    zero_kernel<<<1024, 256>>>();
    degree_kernel<<<(NE + 255) / 256, 256>>>(pins_src, pins_dst, pinned_dst,
                                             connect_src, connect_dst, pt_src, pt_dst, pf_dst);
    xform3<<<592, 256>>>(node_feat, N_CELL, W_pins, W_pt, 0);
    xform3<<<592, 256>>>(hanna_feat, N_GCELL, W_connect, W_connect, 1);
    aker3<<<296, 544>>>(net_feat, hanna_feat, W_topo, b_topo);
    fused_edge<<<5 * (NE * 32 / 256), 256>>>(pins_src, pins_dst, connect_src, connect_dst,
                                             pt_src, pt_dst, pinned_src, pinned_dst,
                                             pf_src, pf_dst, pin_feat, edge_feat);
    fused_final<<<N_CELL * D / 256 + N_NET / 8 + N_GCELL * D / 256, 256>>>(
        out, net_feat, W_net, b_net, b_pins, b_pinned, b_pf, b_connect, b_pt);
}